// round 2
// baseline (speedup 1.0000x reference)
#include <cuda_runtime.h>
#include <cuda_bf16.h>
#include <cstdint>

#define N_ROWS 8192
#define IN_F   2048
#define OUT_F  2048

// ---------------- static device scratch ----------------
__device__ __nv_bfloat16 g_a_hi[N_ROWS * IN_F];   // input hi (bf16)
__device__ __nv_bfloat16 g_a_lo[N_ROWS * IN_F];   // input lo (bf16)
__device__ __nv_bfloat16 g_bt_hi[OUT_F * IN_F];   // Ht[n][k] = H[k][n], hi
__device__ __nv_bfloat16 g_bt_lo[OUT_F * IN_F];   // Ht[n][k] lo

// H[k][n] = s * weight[k/4][comp*512 + n/4]; index = (k%4)*4 + (n%4)
__constant__ unsigned char c_comp[16] = {0,1,2,3, 1,0,3,2, 2,3,0,1, 3,2,1,0};
__constant__ unsigned char c_neg [16] = {0,1,1,1, 0,0,1,0, 0,0,0,1, 0,1,0,0};

// ---------------- prep kernels ----------------
__global__ void split_input_kernel(const float* __restrict__ in) {
    int i = blockIdx.x * blockDim.x + threadIdx.x;
    const int total4 = N_ROWS * IN_F / 4;
    if (i >= total4) return;
    float4 v = reinterpret_cast<const float4*>(in)[i];
    float xs[4] = {v.x, v.y, v.z, v.w};
    ushort4 H, L;
    unsigned short* hp = &H.x;
    unsigned short* lp = &L.x;
#pragma unroll
    for (int j = 0; j < 4; j++) {
        __nv_bfloat16 hb = __float2bfloat16(xs[j]);
        float r = xs[j] - __bfloat162float(hb);
        __nv_bfloat16 lb = __float2bfloat16(r);
        hp[j] = __bfloat16_as_ushort(hb);
        lp[j] = __bfloat16_as_ushort(lb);
    }
    reinterpret_cast<ushort4*>(g_a_hi)[i] = H;
    reinterpret_cast<ushort4*>(g_a_lo)[i] = L;
}

__global__ void build_ht_kernel(const float* __restrict__ w) {
    int idx = blockIdx.x * blockDim.x + threadIdx.x;
    if (idx >= OUT_F * IN_F) return;
    int n = idx >> 11;        // IN_F = 2048
    int k = idx & 2047;
    int t = (k & 3) * 4 + (n & 3);
    int c = c_comp[t];
    float val = __ldg(&w[(k >> 2) * OUT_F + c * 512 + (n >> 2)]);
    if (c_neg[t]) val = -val;
    __nv_bfloat16 hb = __float2bfloat16(val);
    float r = val - __bfloat162float(hb);
    g_bt_hi[idx] = hb;
    g_bt_lo[idx] = __float2bfloat16(r);
}

// ---------------- PTX helpers (sm_80-era, safe at sm_100 base target) --------
__device__ __forceinline__ uint32_t smem_u32(const void* p) {
    uint32_t a;
    asm("{ .reg .u64 t; cvta.to.shared.u64 t, %1; cvt.u32.u64 %0, t; }" : "=r"(a) : "l"(p));
    return a;
}

#define CP_ASYNC16(dst, src) \
    asm volatile("cp.async.cg.shared.global [%0], [%1], 16;" :: "r"(dst), "l"(src))
#define CP_COMMIT() asm volatile("cp.async.commit_group;")
#define CP_WAIT(n)  asm volatile("cp.async.wait_group %0;" :: "n"(n))

__device__ __forceinline__ void ldsm_x4(uint32_t& r0, uint32_t& r1, uint32_t& r2, uint32_t& r3,
                                        uint32_t addr) {
    asm volatile("ldmatrix.sync.aligned.m8n8.x4.shared.b16 {%0,%1,%2,%3}, [%4];"
                 : "=r"(r0), "=r"(r1), "=r"(r2), "=r"(r3) : "r"(addr));
}

__device__ __forceinline__ void hmma(float* c, const uint32_t* a, uint32_t b0, uint32_t b1) {
    asm volatile(
        "mma.sync.aligned.m16n8k16.row.col.f32.bf16.bf16.f32 "
        "{%0,%1,%2,%3}, {%4,%5,%6,%7}, {%8,%9}, {%0,%1,%2,%3};"
        : "+f"(c[0]), "+f"(c[1]), "+f"(c[2]), "+f"(c[3])
        : "r"(a[0]), "r"(a[1]), "r"(a[2]), "r"(a[3]), "r"(b0), "r"(b1));
}

// ---------------- GEMM config ----------------
#define BM 128
#define BN 128
#define BK 32
#define STAGES 4
#define THREADS 256
#define KTILES (IN_F / BK)   // 64

static constexpr int TILE_B  = BM * BK * 2;   // 8192 bytes per bf16 tile
static constexpr int STAGE_B = 4 * TILE_B;    // ahi, alo, bhi, blo = 32 KB
static constexpr int SMEM_TOTAL = STAGES * STAGE_B;  // 128 KB

// Tiles stored as [row][32 k] = 64B rows, 4x 16B chunks; swizzle: chunk ^= (row>>1)&3
__global__ void __launch_bounds__(THREADS, 1) qlinear_gemm(
    const float* __restrict__ bias, float* __restrict__ out)
{
    extern __shared__ char smem[];
    const uint32_t sbase = smem_u32(smem);
    const int tid  = threadIdx.x;
    const int wid  = tid >> 5;
    const int lane = tid & 31;
    const int warp_m = wid & 3;    // 4 warps along M -> 32 rows each
    const int warp_n = wid >> 2;   // 2 warps along N -> 64 cols each
    const int m0 = blockIdx.y * BM;
    const int n0 = blockIdx.x * BN;

    // ---- cp.async source/dst precompute: each thread moves 8x16B per stage ----
    const __nv_bfloat16* gt[4] = {
        g_a_hi  + (size_t)m0 * IN_F,
        g_a_lo  + (size_t)m0 * IN_F,
        g_bt_hi + (size_t)n0 * IN_F,
        g_bt_lo + (size_t)n0 * IN_F
    };
    const int lr = tid >> 2;             // row 0..63 (second half row+64)
    const int lc = tid & 3;              // 16B chunk 0..3
    const uint32_t dst_off = lr * 64 + ((lc ^ ((lr >> 1) & 3)) << 4);  // +4096 for row+64
    const size_t src_off = (size_t)lr * IN_F + lc * 8;                 // elements

    // ---- ldmatrix per-lane addressing ----
    const int g = lane >> 3, r = lane & 7;
    // A: x4 covers 16 m-rows x 16 k; reg order a0..a3
    uint32_t a_row[2], a_sw[2];
    const int a_gbit = g >> 1;           // k-chunk bit
#pragma unroll
    for (int mt = 0; mt < 2; ++mt) {
        int row = warp_m * 32 + mt * 16 + (g & 1) * 8 + r;
        a_row[mt] = row * 64;
        a_sw[mt]  = (row >> 1) & 3;
    }
    // B: x4 covers 16 n-rows x 16 k; regs = (n8 tile, k-half) pairs
    uint32_t b_row[4], b_sw[4];
    const int b_gbit = g & 1;
#pragma unroll
    for (int np = 0; np < 4; ++np) {
        int row = warp_n * 64 + np * 16 + (g >> 1) * 8 + r;
        b_row[np] = row * 64;
        b_sw[np]  = (row >> 1) & 3;
    }

    float acc[2][8][4];
#pragma unroll
    for (int mt = 0; mt < 2; ++mt)
#pragma unroll
        for (int nt = 0; nt < 8; ++nt)
#pragma unroll
            for (int e = 0; e < 4; ++e) acc[mt][nt][e] = 0.0f;

    // ---- stage loader ----
    auto load_stage = [&](int s) {
        const int kc = s * BK;
        const uint32_t sb = sbase + (s & (STAGES - 1)) * STAGE_B;
#pragma unroll
        for (int t = 0; t < 4; ++t) {
            const __nv_bfloat16* gsrc = gt[t] + kc + src_off;
            uint32_t d = sb + t * TILE_B + dst_off;
            CP_ASYNC16(d,        gsrc);
            CP_ASYNC16(d + 4096, gsrc + (size_t)64 * IN_F);
        }
    };

    // prologue: 3 stages in flight
    load_stage(0); CP_COMMIT();
    load_stage(1); CP_COMMIT();
    load_stage(2); CP_COMMIT();

    for (int s = 0; s < KTILES; ++s) {
        CP_WAIT(2);
        __syncthreads();
        if (s + 3 < KTILES) load_stage(s + 3);
        CP_COMMIT();

        const uint32_t sb = sbase + (s & (STAGES - 1)) * STAGE_B;
#pragma unroll
        for (int sk = 0; sk < 2; ++sk) {
            uint32_t ah[2][4], al[2][4], bh[4][4], bl[4][4];
#pragma unroll
            for (int mt = 0; mt < 2; ++mt) {
                uint32_t ca = (uint32_t)(2 * sk + a_gbit);
                uint32_t off = a_row[mt] + ((ca ^ a_sw[mt]) << 4);
                ldsm_x4(ah[mt][0], ah[mt][1], ah[mt][2], ah[mt][3], sb + off);
                ldsm_x4(al[mt][0], al[mt][1], al[mt][2], al[mt][3], sb + TILE_B + off);
            }
#pragma unroll
            for (int np = 0; np < 4; ++np) {
                uint32_t cb = (uint32_t)(2 * sk + b_gbit);
                uint32_t off = b_row[np] + ((cb ^ b_sw[np]) << 4);
                ldsm_x4(bh[np][0], bh[np][1], bh[np][2], bh[np][3], sb + 2 * TILE_B + off);
                ldsm_x4(bl[np][0], bl[np][1], bl[np][2], bl[np][3], sb + 3 * TILE_B + off);
            }
#pragma unroll
            for (int mt = 0; mt < 2; ++mt) {
#pragma unroll
                for (int nt = 0; nt < 8; ++nt) {
                    const int np = nt >> 1, sel = (nt & 1) * 2;
                    hmma(acc[mt][nt], ah[mt], bh[np][sel], bh[np][sel + 1]);
                    hmma(acc[mt][nt], ah[mt], bl[np][sel], bl[np][sel + 1]);
                    hmma(acc[mt][nt], al[mt], bh[np][sel], bh[np][sel + 1]);
                }
            }
        }
    }

    // ---- epilogue: add bias, store fp32 ----
#pragma unroll
    for (int mt = 0; mt < 2; ++mt) {
        int row = m0 + warp_m * 32 + mt * 16 + (lane >> 2);
#pragma unroll
        for (int nt = 0; nt < 8; ++nt) {
            int col = n0 + warp_n * 64 + nt * 8 + (lane & 3) * 2;
            float bx = __ldg(&bias[col]);
            float by = __ldg(&bias[col + 1]);
            float2 v0 = {acc[mt][nt][0] + bx, acc[mt][nt][1] + by};
            float2 v1 = {acc[mt][nt][2] + bx, acc[mt][nt][3] + by};
            *reinterpret_cast<float2*>(out + (size_t)row * OUT_F + col) = v0;
            *reinterpret_cast<float2*>(out + (size_t)(row + 8) * OUT_F + col) = v1;
        }
    }
}

// ---------------- launch ----------------
extern "C" void kernel_launch(void* const* d_in, const int* in_sizes, int n_in,
                              void* d_out, int out_size) {
    (void)in_sizes; (void)n_in; (void)out_size;
    const float* input  = (const float*)d_in[0];
    const float* weight = (const float*)d_in[1];
    const float* bias   = (const float*)d_in[2];
    float* out = (float*)d_out;

    cudaFuncSetAttribute(qlinear_gemm, cudaFuncAttributeMaxDynamicSharedMemorySize, SMEM_TOTAL);

    {
        int total4 = N_ROWS * IN_F / 4;
        split_input_kernel<<<(total4 + 255) / 256, 256>>>(input);
    }
    {
        int total = OUT_F * IN_F;
        build_ht_kernel<<<(total + 255) / 256, 256>>>(weight);
    }
    qlinear_gemm<<<dim3(OUT_F / BN, N_ROWS / BM), THREADS, SMEM_TOTAL>>>(bias, out);
}

// round 3
// speedup vs baseline: 2.2475x; 2.2475x over previous
#include <cuda_runtime.h>
#include <cuda_fp16.h>
#include <cstdint>

#define N_ROWS 8192
#define IN_F   2048
#define OUT_F  2048

// ---------------- static device scratch ----------------
__device__ __half g_a [N_ROWS * IN_F];   // input  (fp16)
__device__ __half g_bt[OUT_F * IN_F];    // Ht[n][k] = H[k][n] (fp16)

// H[k][n] = s * weight[k/4][comp*512 + n/4]; index = (k%4)*4 + (n%4)
__constant__ unsigned char c_comp[16] = {0,1,2,3, 1,0,3,2, 2,3,0,1, 3,2,1,0};
__constant__ unsigned char c_neg [16] = {0,1,1,1, 0,0,1,0, 0,0,0,1, 0,1,0,0};

// ---------------- prep kernels ----------------
__global__ void convert_input_kernel(const float* __restrict__ in) {
    int i = blockIdx.x * blockDim.x + threadIdx.x;
    const int total4 = N_ROWS * IN_F / 4;
    if (i >= total4) return;
    float4 v = reinterpret_cast<const float4*>(in)[i];
    __half2 h0 = __floats2half2_rn(v.x, v.y);
    __half2 h1 = __floats2half2_rn(v.z, v.w);
    uint2 o;
    o.x = reinterpret_cast<uint32_t&>(h0);
    o.y = reinterpret_cast<uint32_t&>(h1);
    reinterpret_cast<uint2*>(g_a)[i] = o;
}

__global__ void build_ht_kernel(const float* __restrict__ w) {
    int idx = blockIdx.x * blockDim.x + threadIdx.x;
    if (idx >= OUT_F * IN_F) return;
    int n = idx >> 11;        // IN_F = 2048
    int k = idx & 2047;
    int t = (k & 3) * 4 + (n & 3);
    int c = c_comp[t];
    float val = __ldg(&w[(k >> 2) * OUT_F + c * 512 + (n >> 2)]);
    if (c_neg[t]) val = -val;
    g_bt[idx] = __float2half_rn(val);
}

// ---------------- PTX helpers ----------------
__device__ __forceinline__ uint32_t smem_u32(const void* p) {
    uint32_t a;
    asm("{ .reg .u64 t; cvta.to.shared.u64 t, %1; cvt.u32.u64 %0, t; }" : "=r"(a) : "l"(p));
    return a;
}

#define CP_ASYNC16(dst, src) \
    asm volatile("cp.async.cg.shared.global [%0], [%1], 16;" :: "r"(dst), "l"(src))
#define CP_COMMIT() asm volatile("cp.async.commit_group;")
#define CP_WAIT(n)  asm volatile("cp.async.wait_group %0;" :: "n"(n))

__device__ __forceinline__ void ldsm_x4(uint32_t& r0, uint32_t& r1, uint32_t& r2, uint32_t& r3,
                                        uint32_t addr) {
    asm volatile("ldmatrix.sync.aligned.m8n8.x4.shared.b16 {%0,%1,%2,%3}, [%4];"
                 : "=r"(r0), "=r"(r1), "=r"(r2), "=r"(r3) : "r"(addr));
}

__device__ __forceinline__ void hmma(float* c, const uint32_t* a, uint32_t b0, uint32_t b1) {
    asm volatile(
        "mma.sync.aligned.m16n8k16.row.col.f32.f16.f16.f32 "
        "{%0,%1,%2,%3}, {%4,%5,%6,%7}, {%8,%9}, {%0,%1,%2,%3};"
        : "+f"(c[0]), "+f"(c[1]), "+f"(c[2]), "+f"(c[3])
        : "r"(a[0]), "r"(a[1]), "r"(a[2]), "r"(a[3]), "r"(b0), "r"(b1));
}

// ---------------- GEMM config ----------------
#define BM 128
#define BN 128
#define BK 32
#define STAGES 8
#define THREADS 256
#define KTILES (IN_F / BK)   // 64

static constexpr int TILE_B  = BM * BK * 2;   // 8192 bytes per fp16 tile
static constexpr int STAGE_B = 2 * TILE_B;    // A + B = 16 KB
static constexpr int SMEM_TOTAL = STAGES * STAGE_B;  // 128 KB

// Tiles stored as [row][32 k] = 64B rows, 4x 16B chunks; swizzle: chunk ^= (row>>1)&3
__global__ void __launch_bounds__(THREADS, 1) qlinear_gemm(
    const float* __restrict__ bias, float* __restrict__ out)
{
    extern __shared__ char smem[];
    const uint32_t sbase = smem_u32(smem);
    const int tid  = threadIdx.x;
    const int wid  = tid >> 5;
    const int lane = tid & 31;
    const int warp_m = wid & 3;    // 4 warps along M -> 32 rows each
    const int warp_n = wid >> 2;   // 2 warps along N -> 64 cols each
    const int m0 = blockIdx.y * BM;
    const int n0 = blockIdx.x * BN;

    // ---- cp.async: each thread moves 2x16B per tile, 2 tiles per stage ----
    const __half* gt[2] = {
        g_a  + (size_t)m0 * IN_F,
        g_bt + (size_t)n0 * IN_F
    };
    const int lr = tid >> 2;             // row 0..63 (second half row+64)
    const int lc = tid & 3;              // 16B chunk 0..3
    const uint32_t dst_off = lr * 64 + ((lc ^ ((lr >> 1) & 3)) << 4);
    const size_t src_off = (size_t)lr * IN_F + lc * 8;  // elements

    // ---- ldmatrix per-lane addressing (verified fragment layout) ----
    const int g = lane >> 3, r = lane & 7;
    // A: reg i -> (m-half = i&1, k-half = i>>1); row uses (g&1), chunk bit (g>>1)
    uint32_t a_row[2], a_sw[2];
    const int a_gbit = g >> 1;
#pragma unroll
    for (int mt = 0; mt < 2; ++mt) {
        int row = warp_m * 32 + mt * 16 + (g & 1) * 8 + r;
        a_row[mt] = row * 64;
        a_sw[mt]  = (row >> 1) & 3;
    }
    // B: reg i -> (k-half = i&1, n-half = i>>1); row uses (g>>1), chunk bit (g&1)
    uint32_t b_row[4], b_sw[4];
    const int b_gbit = g & 1;
#pragma unroll
    for (int np = 0; np < 4; ++np) {
        int row = warp_n * 64 + np * 16 + (g >> 1) * 8 + r;
        b_row[np] = row * 64;
        b_sw[np]  = (row >> 1) & 3;
    }

    float acc[2][8][4];
#pragma unroll
    for (int mt = 0; mt < 2; ++mt)
#pragma unroll
        for (int nt = 0; nt < 8; ++nt)
#pragma unroll
            for (int e = 0; e < 4; ++e) acc[mt][nt][e] = 0.0f;

    // ---- stage loader ----
    auto load_stage = [&](int s) {
        const int kc = s * BK;
        const uint32_t sb = sbase + (s & (STAGES - 1)) * STAGE_B;
#pragma unroll
        for (int t = 0; t < 2; ++t) {
            const __half* gsrc = gt[t] + kc + src_off;
            uint32_t d = sb + t * TILE_B + dst_off;
            CP_ASYNC16(d,        gsrc);
            CP_ASYNC16(d + 4096, gsrc + (size_t)64 * IN_F);
        }
    };

    // prologue: 7 stages in flight
#pragma unroll
    for (int s = 0; s < STAGES - 1; ++s) { load_stage(s); CP_COMMIT(); }

    for (int s = 0; s < KTILES; ++s) {
        CP_WAIT(STAGES - 2);
        __syncthreads();
        if (s + STAGES - 1 < KTILES) load_stage(s + STAGES - 1);
        CP_COMMIT();

        const uint32_t sb = sbase + (s & (STAGES - 1)) * STAGE_B;
#pragma unroll
        for (int sk = 0; sk < 2; ++sk) {
            uint32_t ah[2][4], bh[4][4];
#pragma unroll
            for (int mt = 0; mt < 2; ++mt) {
                uint32_t ca = (uint32_t)(2 * sk + a_gbit);
                uint32_t off = a_row[mt] + ((ca ^ a_sw[mt]) << 4);
                ldsm_x4(ah[mt][0], ah[mt][1], ah[mt][2], ah[mt][3], sb + off);
            }
#pragma unroll
            for (int np = 0; np < 4; ++np) {
                uint32_t cb = (uint32_t)(2 * sk + b_gbit);
                uint32_t off = b_row[np] + ((cb ^ b_sw[np]) << 4);
                ldsm_x4(bh[np][0], bh[np][1], bh[np][2], bh[np][3], sb + TILE_B + off);
            }
#pragma unroll
            for (int mt = 0; mt < 2; ++mt) {
#pragma unroll
                for (int nt = 0; nt < 8; ++nt) {
                    const int np = nt >> 1, sel = (nt & 1) * 2;
                    hmma(acc[mt][nt], ah[mt], bh[np][sel], bh[np][sel + 1]);
                }
            }
        }
    }

    // ---- epilogue: add bias, store fp32 ----
#pragma unroll
    for (int mt = 0; mt < 2; ++mt) {
        int row = m0 + warp_m * 32 + mt * 16 + (lane >> 2);
#pragma unroll
        for (int nt = 0; nt < 8; ++nt) {
            int col = n0 + warp_n * 64 + nt * 8 + (lane & 3) * 2;
            float bx = __ldg(&bias[col]);
            float by = __ldg(&bias[col + 1]);
            float2 v0 = {acc[mt][nt][0] + bx, acc[mt][nt][1] + by};
            float2 v1 = {acc[mt][nt][2] + bx, acc[mt][nt][3] + by};
            *reinterpret_cast<float2*>(out + (size_t)row * OUT_F + col) = v0;
            *reinterpret_cast<float2*>(out + (size_t)(row + 8) * OUT_F + col) = v1;
        }
    }
}

// ---------------- launch ----------------
extern "C" void kernel_launch(void* const* d_in, const int* in_sizes, int n_in,
                              void* d_out, int out_size) {
    (void)in_sizes; (void)n_in; (void)out_size;
    const float* input  = (const float*)d_in[0];
    const float* weight = (const float*)d_in[1];
    const float* bias   = (const float*)d_in[2];
    float* out = (float*)d_out;

    cudaFuncSetAttribute(qlinear_gemm, cudaFuncAttributeMaxDynamicSharedMemorySize, SMEM_TOTAL);

    {
        int total4 = N_ROWS * IN_F / 4;
        convert_input_kernel<<<(total4 + 255) / 256, 256>>>(input);
    }
    {
        int total = OUT_F * IN_F;
        build_ht_kernel<<<(total + 255) / 256, 256>>>(weight);
    }
    qlinear_gemm<<<dim3(OUT_F / BN, N_ROWS / BM), THREADS, SMEM_TOTAL>>>(bias, out);
}